// round 15
// baseline (speedup 1.0000x reference)
#include <cuda_runtime.h>
#include <cstdint>

// CenterLoss: mean_i ||x[i] - centers[labels[i]]||^2
// B=16384, C=4000, D=512
// Inputs: x [B*D] f32, labels [B] int32, centers [C*D] f32. Output: scalar f32.
//
// Body = proven-best R2 (warp/row, 8 front-batched LDG.128). Epilogue replaces
// the memsetAsync graph node: blocks atomicAdd into a device accumulator; the
// last-arriving block (counter election) writes out and resets state. One
// graph node instead of two.

#define B_ROWS 16384
#define C_ROWS 4000
#define D_VEC  128               // 512 floats = 128 float4 per row
#define WARPS_PER_BLOCK 8
#define THREADS (WARPS_PER_BLOCK * 32)
#define BLOCKS  (B_ROWS / WARPS_PER_BLOCK)   // 2048

__device__ float    g_accum;    // zero at load; self-resets each run
__device__ unsigned g_count;    // zero at load; self-resets each run

__global__ __launch_bounds__(THREADS)
void center_loss_kernel(const float4* __restrict__ x,
                        const int* __restrict__ labels,
                        const float4* __restrict__ centers,
                        float* __restrict__ out)
{
    const int warp = threadIdx.x >> 5;
    const int lane = threadIdx.x & 31;
    const int row  = blockIdx.x * WARPS_PER_BLOCK + warp;

    int lab = labels[row];
    lab = min(max(lab, 0), C_ROWS - 1);

    const float4* xr = x       + (size_t)row * D_VEC + lane;
    const float4* cr = centers + (size_t)lab * D_VEC + lane;

    // Proven-best body: 8 front-batched LDG.128 per lane.
    float4 a0 = xr[0],  a1 = xr[32], a2 = xr[64], a3 = xr[96];
    float4 b0 = cr[0],  b1 = cr[32], b2 = cr[64], b3 = cr[96];

    float s = 0.0f;
    float dx, dy, dz, dw;
    dx = a0.x - b0.x; dy = a0.y - b0.y; dz = a0.z - b0.z; dw = a0.w - b0.w;
    s += dx*dx + dy*dy + dz*dz + dw*dw;
    dx = a1.x - b1.x; dy = a1.y - b1.y; dz = a1.z - b1.z; dw = a1.w - b1.w;
    s += dx*dx + dy*dy + dz*dz + dw*dw;
    dx = a2.x - b2.x; dy = a2.y - b2.y; dz = a2.z - b2.z; dw = a2.w - b2.w;
    s += dx*dx + dy*dy + dz*dz + dw*dw;
    dx = a3.x - b3.x; dy = a3.y - b3.y; dz = a3.z - b3.z; dw = a3.w - b3.w;
    s += dx*dx + dy*dy + dz*dz + dw*dw;

    #pragma unroll
    for (int o = 16; o > 0; o >>= 1)
        s += __shfl_xor_sync(0xFFFFFFFFu, s, o);

    __shared__ float warp_sums[WARPS_PER_BLOCK];
    if (lane == 0) warp_sums[warp] = s;
    __syncthreads();

    if (threadIdx.x == 0) {
        float v = 0.0f;
        #pragma unroll
        for (int w = 0; w < WARPS_PER_BLOCK; w++) v += warp_sums[w];

        atomicAdd(&g_accum, v);          // accumulate global sum
        __threadfence();                 // my add visible before my arrival
        unsigned old = atomicAdd(&g_count, 1u);
        if (old == BLOCKS - 1) {
            __threadfence();             // all adds visible (each fenced pre-arrive)
            float total = atomicAdd(&g_accum, 0.0f);   // coherent read
            *out = total * (1.0f / (float)B_ROWS);
            atomicExch(&g_accum, 0.0f);  // reset for next replay
            atomicExch(&g_count, 0u);
        }
    }
}

extern "C" void kernel_launch(void* const* d_in, const int* in_sizes, int n_in,
                              void* d_out, int out_size)
{
    const float4* x       = (const float4*)d_in[0];
    const int*    labels  = (const int*)d_in[1];
    const float4* centers = (const float4*)d_in[2];
    float*        out     = (float*)d_out;

    // Single graph node: no memset.
    center_loss_kernel<<<BLOCKS, THREADS>>>(x, labels, centers, out);
}

// round 16
// speedup vs baseline: 1.1080x; 1.1080x over previous
#include <cuda_runtime.h>
#include <cstdint>

// CenterLoss: mean_i ||x[i] - centers[labels[i]]||^2
// B=16384, C=4000, D=512
// Inputs: x [B*D] f32, labels [B] int32, centers [C*D] f32. Output: scalar f32.
//
// FINAL: proven-best configuration (R2, 10.18us). Session evidence (15
// experiments spanning LDG/LDGSTS/TMA paths, 1KB-130KB in-flight per SM,
// occ 20-78%, cache policies, prefetch, epilogue variants) shows this box
// sustains ~4 TB/s DRAM service for this workload; mandatory traffic is
// 40MB (x streamed once + centers gathered once) -> ~10us machine floor.
// This kernel sits on that floor; all structural deviations measured
// neutral or worse.

#define B_ROWS 16384
#define C_ROWS 4000
#define D_VEC  128               // 512 floats = 128 float4 per row
#define WARPS_PER_BLOCK 8
#define THREADS (WARPS_PER_BLOCK * 32)
#define BLOCKS  (B_ROWS / WARPS_PER_BLOCK)   // 2048

__global__ __launch_bounds__(THREADS)
void center_loss_kernel(const float4* __restrict__ x,
                        const int* __restrict__ labels,
                        const float4* __restrict__ centers,
                        float* __restrict__ out)
{
    const int warp = threadIdx.x >> 5;
    const int lane = threadIdx.x & 31;
    const int row  = blockIdx.x * WARPS_PER_BLOCK + warp;

    int lab = labels[row];
    lab = min(max(lab, 0), C_ROWS - 1);     // defensive clamp, ~free

    const float4* xr = x       + (size_t)row * D_VEC;
    const float4* cr = centers + (size_t)lab * D_VEC;

    // Front-batched 8 LDG.128 per lane: warp covers the full 2KB row per side.
    float4 a0 = xr[lane];
    float4 a1 = xr[lane + 32];
    float4 a2 = xr[lane + 64];
    float4 a3 = xr[lane + 96];
    float4 b0 = cr[lane];
    float4 b1 = cr[lane + 32];
    float4 b2 = cr[lane + 64];
    float4 b3 = cr[lane + 96];

    float s = 0.0f;
    float dx, dy, dz, dw;
    dx = a0.x - b0.x; dy = a0.y - b0.y; dz = a0.z - b0.z; dw = a0.w - b0.w;
    s += dx*dx + dy*dy + dz*dz + dw*dw;
    dx = a1.x - b1.x; dy = a1.y - b1.y; dz = a1.z - b1.z; dw = a1.w - b1.w;
    s += dx*dx + dy*dy + dz*dz + dw*dw;
    dx = a2.x - b2.x; dy = a2.y - b2.y; dz = a2.z - b2.z; dw = a2.w - b2.w;
    s += dx*dx + dy*dy + dz*dz + dw*dw;
    dx = a3.x - b3.x; dy = a3.y - b3.y; dz = a3.z - b3.z; dw = a3.w - b3.w;
    s += dx*dx + dy*dy + dz*dz + dw*dw;

    // warp reduce
    #pragma unroll
    for (int o = 16; o > 0; o >>= 1)
        s += __shfl_xor_sync(0xFFFFFFFFu, s, o);

    __shared__ float warp_sums[WARPS_PER_BLOCK];
    if (lane == 0) warp_sums[warp] = s;
    __syncthreads();

    if (warp == 0) {
        float v = (lane < WARPS_PER_BLOCK) ? warp_sums[lane] : 0.0f;
        #pragma unroll
        for (int o = 4; o > 0; o >>= 1)
            v += __shfl_xor_sync(0xFFFFFFFFu, v, o);
        if (lane == 0)
            atomicAdd(out, v * (1.0f / (float)B_ROWS));
    }
}

extern "C" void kernel_launch(void* const* d_in, const int* in_sizes, int n_in,
                              void* d_out, int out_size)
{
    const float4* x       = (const float4*)d_in[0];
    const int*    labels  = (const int*)d_in[1];
    const float4* centers = (const float4*)d_in[2];
    float*        out     = (float*)d_out;

    cudaMemsetAsync(out, 0, sizeof(float));
    center_loss_kernel<<<BLOCKS, THREADS>>>(x, labels, centers, out);
}

// round 17
// speedup vs baseline: 1.2422x; 1.1211x over previous
#include <cuda_runtime.h>
#include <cstdint>

// CenterLoss: mean_i ||x[i] - centers[labels[i]]||^2
// B=16384, C=4000, D=512
// Inputs: x [B*D] f32, labels [B] int32, centers [C*D] f32. Output: scalar f32.
//
// FINAL (proven-best, R2 configuration). Session evidence: 15 structural
// experiments (LDG/LDGSTS/TMA paths, in-flight 1KB-130KB/SM, occ 20-78%,
// cache policies, prefetch, epilogue variants) all pin at ~3.9-4.1 TB/s
// kernel-internal; mandatory traffic is 40MB -> ~10.5us machine floor.
// Timed results carry ~±0.7us replay variance around that floor. This
// kernel sits on the floor; every deviation measured neutral or worse.

#define B_ROWS 16384
#define C_ROWS 4000
#define D_VEC  128               // 512 floats = 128 float4 per row
#define WARPS_PER_BLOCK 8
#define THREADS (WARPS_PER_BLOCK * 32)
#define BLOCKS  (B_ROWS / WARPS_PER_BLOCK)   // 2048

__global__ __launch_bounds__(THREADS)
void center_loss_kernel(const float4* __restrict__ x,
                        const int* __restrict__ labels,
                        const float4* __restrict__ centers,
                        float* __restrict__ out)
{
    const int warp = threadIdx.x >> 5;
    const int lane = threadIdx.x & 31;
    const int row  = blockIdx.x * WARPS_PER_BLOCK + warp;

    int lab = labels[row];
    lab = min(max(lab, 0), C_ROWS - 1);     // defensive clamp, ~free

    const float4* xr = x       + (size_t)row * D_VEC;
    const float4* cr = centers + (size_t)lab * D_VEC;

    // Front-batched 8 LDG.128 per lane: warp covers the full 2KB row per side.
    float4 a0 = xr[lane];
    float4 a1 = xr[lane + 32];
    float4 a2 = xr[lane + 64];
    float4 a3 = xr[lane + 96];
    float4 b0 = cr[lane];
    float4 b1 = cr[lane + 32];
    float4 b2 = cr[lane + 64];
    float4 b3 = cr[lane + 96];

    float s = 0.0f;
    float dx, dy, dz, dw;
    dx = a0.x - b0.x; dy = a0.y - b0.y; dz = a0.z - b0.z; dw = a0.w - b0.w;
    s += dx*dx + dy*dy + dz*dz + dw*dw;
    dx = a1.x - b1.x; dy = a1.y - b1.y; dz = a1.z - b1.z; dw = a1.w - b1.w;
    s += dx*dx + dy*dy + dz*dz + dw*dw;
    dx = a2.x - b2.x; dy = a2.y - b2.y; dz = a2.z - b2.z; dw = a2.w - b2.w;
    s += dx*dx + dy*dy + dz*dz + dw*dw;
    dx = a3.x - b3.x; dy = a3.y - b3.y; dz = a3.z - b3.z; dw = a3.w - b3.w;
    s += dx*dx + dy*dy + dz*dz + dw*dw;

    // warp reduce
    #pragma unroll
    for (int o = 16; o > 0; o >>= 1)
        s += __shfl_xor_sync(0xFFFFFFFFu, s, o);

    __shared__ float warp_sums[WARPS_PER_BLOCK];
    if (lane == 0) warp_sums[warp] = s;
    __syncthreads();

    if (warp == 0) {
        float v = (lane < WARPS_PER_BLOCK) ? warp_sums[lane] : 0.0f;
        #pragma unroll
        for (int o = 4; o > 0; o >>= 1)
            v += __shfl_xor_sync(0xFFFFFFFFu, v, o);
        if (lane == 0)
            atomicAdd(out, v * (1.0f / (float)B_ROWS));
    }
}

extern "C" void kernel_launch(void* const* d_in, const int* in_sizes, int n_in,
                              void* d_out, int out_size)
{
    const float4* x       = (const float4*)d_in[0];
    const int*    labels  = (const int*)d_in[1];
    const float4* centers = (const float4*)d_in[2];
    float*        out     = (float*)d_out;

    cudaMemsetAsync(out, 0, sizeof(float));
    center_loss_kernel<<<BLOCKS, THREADS>>>(x, labels, centers, out);
}